// round 1
// baseline (speedup 1.0000x reference)
#include <cuda_runtime.h>

// ---------------------------------------------------------------------------
// Shapes (fixed for this problem)
// ---------------------------------------------------------------------------
#define B_   4
#define V_   256
#define H_   128      // hidden dim of both EdgeConv layers
#define KE_  32       // edge-attr channels C2
#define JC_  128      // j-chunk processed per phase in ec_kernel
#define ST_T 132      // sT row stride (128 + 4 pad, float4-aligned)
#define ST_E 33       // sE row stride (32 + 1 pad)
#define H2_  256      // pair-MLP hidden

// ---------------------------------------------------------------------------
// Device scratch (allocation-free rule: __device__ globals)
// ---------------------------------------------------------------------------
__device__ float g_P [B_*V_*H_];
__device__ float g_Q [B_*V_*H_];
__device__ float g_X1[B_*V_*H_];
__device__ float g_X2[B_*V_*H_];
__device__ float g_R [B_*V_*H2_];
__device__ float g_S [B_*V_*H2_];

// ---------------------------------------------------------------------------
// f32x2 packed-FMA helpers (FFMA2: 2 fp32 MACs per instruction on sm_103a)
// ---------------------------------------------------------------------------
using ull = unsigned long long;

__device__ __forceinline__ ull pack2(float x) {
    ull r; asm("mov.b64 %0, {%1, %1};" : "=l"(r) : "f"(x)); return r;
}
__device__ __forceinline__ ull ffma2(ull a, ull b, ull c) {
    ull d; asm("fma.rn.f32x2 %0, %1, %2, %3;" : "=l"(d) : "l"(a), "l"(b), "l"(c));
    return d;
}
__device__ __forceinline__ float2 unpack2(ull v) {
    float2 r; asm("mov.b64 {%0, %1}, %2;" : "=f"(r.x), "=f"(r.y) : "l"(v));
    return r;
}

// ---------------------------------------------------------------------------
// Per-node precompute for an EdgeConv layer:
//   P[n,h] = x[n,:] @ (W1[0:C] - W1[C:2C]) + b1   (x_i coefficient)
//   Q[n,h] = x[n,:] @  W1[C:2C]                    (x_j coefficient)
// grid = B*V/4, block = 128 (one thread per h), 4 nodes per block
// ---------------------------------------------------------------------------
__global__ void pq_kernel(const float* __restrict__ x, const float* __restrict__ W1,
                          const float* __restrict__ b1, int C_in,
                          float* __restrict__ P, float* __restrict__ Q)
{
    __shared__ float sx[4][128];
    const int h = threadIdx.x;
    const int base = blockIdx.x * 4;
    #pragma unroll
    for (int r = 0; r < 4; ++r)
        if (h < C_in) sx[r][h] = x[(size_t)(base + r) * C_in + h];
    __syncthreads();

    float bb = b1[h];
    float p0 = bb, p1 = bb, p2 = bb, p3 = bb;
    float q0 = 0.f, q1 = 0.f, q2 = 0.f, q3 = 0.f;
    for (int c = 0; c < C_in; ++c) {
        float wa = W1[c * H_ + h];
        float wb = W1[(C_in + c) * H_ + h];
        float wd = wa - wb;
        p0 += sx[0][c] * wd;  q0 += sx[0][c] * wb;
        p1 += sx[1][c] * wd;  q1 += sx[1][c] * wb;
        p2 += sx[2][c] * wd;  q2 += sx[2][c] * wb;
        p3 += sx[3][c] * wd;  q3 += sx[3][c] * wb;
    }
    P[(size_t)(base+0)*H_ + h] = p0;  Q[(size_t)(base+0)*H_ + h] = q0;
    P[(size_t)(base+1)*H_ + h] = p1;  Q[(size_t)(base+1)*H_ + h] = q1;
    P[(size_t)(base+2)*H_ + h] = p2;  Q[(size_t)(base+2)*H_ + h] = q2;
    P[(size_t)(base+3)*H_ + h] = p3;  Q[(size_t)(base+3)*H_ + h] = q3;
}

// ---------------------------------------------------------------------------
// Fused EdgeConv main kernel. One CTA per (b, i).
//   T[j,c] = relu(P[i,c] + Q[j,c] + e[b,i,j,:] @ W1c)     (phase 1, K=32)
//   H[j,c] = relu(T[j,:] @ W2 + b2)                        (phase 2, K=128)
//   Xout[b,i,c] = masked-max_j H[j,c]   (adj mask; all-masked -> 0)
// 256 threads, 16x16 thread grid, 8x8 register tiles, f32x2 packed FMAs.
// ---------------------------------------------------------------------------
__global__ void __launch_bounds__(256, 1)
ec_kernel(const float* __restrict__ Pg, const float* __restrict__ Qg,
          const float* __restrict__ E, const float* __restrict__ W1c,
          const float* __restrict__ W2, const float* __restrict__ b2,
          const int* __restrict__ adj, float* __restrict__ Xout)
{
    extern __shared__ float sm[];
    float* sW1c = sm;                        // 32*128      = 4096
    float* sW2  = sW1c + KE_*H_;             // 128*128     = 16384
    float* sT   = sW2  + H_*H_;              // 128*132     = 16896
    float* sE   = sT   + JC_*ST_T;           // 128*33      = 4224
    float* sP   = sE   + JC_*ST_E;           // 128
    float* sB2  = sP   + H_;                 // 128
    int*   sAdj = (int*)(sB2 + H_);          // 256
    float* sRed = sE;                        // reuse (needs 16*128 <= 4224)

    const int tid = threadIdx.x;
    const int bi  = blockIdx.x;              // b*V + i
    const int b   = bi >> 8;

    #pragma unroll 4
    for (int idx = tid; idx < KE_*H_; idx += 256) sW1c[idx] = W1c[idx];
    #pragma unroll 8
    for (int idx = tid; idx < H_*H_; idx += 256) sW2[idx] = W2[idx];
    if (tid < H_) { sP[tid] = Pg[(size_t)bi*H_ + tid]; sB2[tid] = b2[tid]; }
    sAdj[tid] = adj[(size_t)bi*V_ + tid];

    const int ty = tid >> 4, tx = tid & 15;
    const int j0 = ty << 3, c0 = tx << 3;

    float rmax[8];
    #pragma unroll
    for (int p = 0; p < 8; ++p) rmax[p] = -1e9f;

    for (int chunk = 0; chunk < V_/JC_; ++chunk) {
        const int jbase = chunk * JC_;
        __syncthreads();
        // load E chunk (rows jbase..jbase+127) into sE[j][k]
        const float* Erow = E + ((size_t)bi * V_ + jbase) * KE_;
        #pragma unroll 4
        for (int idx = tid; idx < JC_*KE_; idx += 256) {
            int j = idx >> 5, k = idx & 31;
            sE[j*ST_E + k] = Erow[idx];
        }
        __syncthreads();

        // ---- phase 1: E @ W1c (K=32) ----
        ull acc[8][4];
        #pragma unroll
        for (int jj = 0; jj < 8; ++jj)
            #pragma unroll
            for (int p = 0; p < 4; ++p) acc[jj][p] = 0ULL;

        #pragma unroll 2
        for (int k = 0; k < KE_; ++k) {
            const ulonglong2 bb0 = *(const ulonglong2*)&sW1c[k*H_ + c0];
            const ulonglong2 bb1 = *(const ulonglong2*)&sW1c[k*H_ + c0 + 4];
            const ull bv0 = bb0.x, bv1 = bb0.y, bv2 = bb1.x, bv3 = bb1.y;
            #pragma unroll
            for (int jj = 0; jj < 8; ++jj) {
                ull a2 = pack2(sE[(j0+jj)*ST_E + k]);
                acc[jj][0] = ffma2(a2, bv0, acc[jj][0]);
                acc[jj][1] = ffma2(a2, bv1, acc[jj][1]);
                acc[jj][2] = ffma2(a2, bv2, acc[jj][2]);
                acc[jj][3] = ffma2(a2, bv3, acc[jj][3]);
            }
        }

        // epilogue: T = relu(acc + P + Q) -> sT
        #pragma unroll
        for (int jj = 0; jj < 8; ++jj) {
            const float* q = Qg + ((size_t)b*V_ + jbase + j0 + jj)*H_ + c0;
            float4 q0v = *(const float4*)(q);
            float4 q1v = *(const float4*)(q + 4);
            float qv[8] = {q0v.x,q0v.y,q0v.z,q0v.w,q1v.x,q1v.y,q1v.z,q1v.w};
            float* trow = sT + (j0+jj)*ST_T + c0;
            #pragma unroll
            for (int p = 0; p < 4; ++p) {
                float2 av = unpack2(acc[jj][p]);
                trow[2*p]   = fmaxf(av.x + sP[c0+2*p]   + qv[2*p],   0.f);
                trow[2*p+1] = fmaxf(av.y + sP[c0+2*p+1] + qv[2*p+1], 0.f);
            }
        }
        __syncthreads();

        // ---- phase 2: T @ W2 (K=128) ----
        #pragma unroll
        for (int jj = 0; jj < 8; ++jj)
            #pragma unroll
            for (int p = 0; p < 4; ++p) acc[jj][p] = 0ULL;

        #pragma unroll 2
        for (int k = 0; k < H_; ++k) {
            const ulonglong2 bb0 = *(const ulonglong2*)&sW2[k*H_ + c0];
            const ulonglong2 bb1 = *(const ulonglong2*)&sW2[k*H_ + c0 + 4];
            const ull bv0 = bb0.x, bv1 = bb0.y, bv2 = bb1.x, bv3 = bb1.y;
            #pragma unroll
            for (int jj = 0; jj < 8; ++jj) {
                ull a2 = pack2(sT[(j0+jj)*ST_T + k]);
                acc[jj][0] = ffma2(a2, bv0, acc[jj][0]);
                acc[jj][1] = ffma2(a2, bv1, acc[jj][1]);
                acc[jj][2] = ffma2(a2, bv2, acc[jj][2]);
                acc[jj][3] = ffma2(a2, bv3, acc[jj][3]);
            }
        }

        // epilogue: relu(+b2), adjacency-masked running max over j
        #pragma unroll
        for (int jj = 0; jj < 8; ++jj) {
            if (sAdj[jbase + j0 + jj] > 0) {
                #pragma unroll
                for (int p = 0; p < 4; ++p) {
                    float2 hv = unpack2(acc[jj][p]);
                    float h0 = fmaxf(hv.x + sB2[c0+2*p],   0.f);
                    float h1 = fmaxf(hv.y + sB2[c0+2*p+1], 0.f);
                    rmax[2*p]   = fmaxf(rmax[2*p],   h0);
                    rmax[2*p+1] = fmaxf(rmax[2*p+1], h1);
                }
            }
        }
    }

    // cross-thread (over ty / j-tiles) max reduction
    __syncthreads();
    #pragma unroll
    for (int p = 0; p < 8; ++p) sRed[ty*H_ + c0 + p] = rmax[p];
    __syncthreads();
    for (int s = 8; s > 0; s >>= 1) {
        if (ty < s) {
            #pragma unroll
            for (int p = 0; p < 8; ++p) {
                float a = sRed[ty*H_ + c0 + p];
                float o = sRed[(ty+s)*H_ + c0 + p];
                sRed[ty*H_ + c0 + p] = fmaxf(a, o);
            }
        }
        __syncthreads();
    }
    if (ty == 0) {
        #pragma unroll
        for (int p = 0; p < 8; ++p) {
            float v = sRed[c0 + p];
            Xout[(size_t)bi*H_ + c0 + p] = (v < -1e8f) ? 0.f : v;
        }
    }
}

// ---------------------------------------------------------------------------
// Pair-MLP precompute:
//   R[n,m] = x2[n,:] @ h3_W[0:128,  m]            (x_j part)
//   S[n,m] = x2[n,:] @ h3_W[128:256,m] + h3_b[m]  (x_i part)
// grid = B*V/4, block = 256 (one thread per m), 4 nodes per block
// ---------------------------------------------------------------------------
__global__ void rs_kernel(const float* __restrict__ x, const float* __restrict__ W3,
                          const float* __restrict__ b3,
                          float* __restrict__ R, float* __restrict__ S)
{
    __shared__ float sx[4][128];
    const int m = threadIdx.x;
    const int base = blockIdx.x * 4;
    if (m < 128) {
        #pragma unroll
        for (int r = 0; r < 4; ++r)
            sx[r][m] = x[(size_t)(base + r) * H_ + m];
    }
    __syncthreads();

    float r0 = 0.f, r1 = 0.f, r2 = 0.f, r3 = 0.f;
    float bb = b3[m];
    float s0 = bb, s1 = bb, s2 = bb, s3 = bb;
    for (int c = 0; c < 128; ++c) {
        float wa = W3[c * H2_ + m];
        float wb = W3[(128 + c) * H2_ + m];
        r0 += sx[0][c]*wa;  s0 += sx[0][c]*wb;
        r1 += sx[1][c]*wa;  s1 += sx[1][c]*wb;
        r2 += sx[2][c]*wa;  s2 += sx[2][c]*wb;
        r3 += sx[3][c]*wa;  s3 += sx[3][c]*wb;
    }
    R[(size_t)(base+0)*H2_ + m] = r0;  S[(size_t)(base+0)*H2_ + m] = s0;
    R[(size_t)(base+1)*H2_ + m] = r1;  S[(size_t)(base+1)*H2_ + m] = s1;
    R[(size_t)(base+2)*H2_ + m] = r2;  S[(size_t)(base+2)*H2_ + m] = s2;
    R[(size_t)(base+3)*H2_ + m] = r3;  S[(size_t)(base+3)*H2_ + m] = s3;
}

// ---------------------------------------------------------------------------
// Pair scoring: out[b,i,j] = sigmoid( sum_m relu(R[j,m]+S[i,m]) * outW[m] + outB )
// grid = (V/IL, B), block = 256 (one thread per j), IL i-rows per CTA.
// ---------------------------------------------------------------------------
#define IL_ 8
#define MC_ 32

__global__ void __launch_bounds__(256)
pair_kernel(const float* __restrict__ R, const float* __restrict__ S,
            const float* __restrict__ outW, const float* __restrict__ outB,
            float* __restrict__ out)
{
    __shared__ float sR[V_][MC_ + 1];
    __shared__ float sS[IL_][MC_ + 1];
    __shared__ float sw[MC_];

    const int tid = threadIdx.x;   // == j
    const int b   = blockIdx.y;
    const int i0  = blockIdx.x * IL_;

    float acc[IL_];
    #pragma unroll
    for (int il = 0; il < IL_; ++il) acc[il] = 0.f;

    for (int mc = 0; mc < H2_; mc += MC_) {
        __syncthreads();
        #pragma unroll 4
        for (int idx = tid; idx < V_*MC_; idx += 256) {
            int j = idx >> 5, mm = idx & (MC_-1);
            sR[j][mm] = R[((size_t)b*V_ + j)*H2_ + mc + mm];
        }
        if (tid < IL_*MC_) {
            int il = tid >> 5, mm = tid & (MC_-1);
            sS[il][mm] = S[((size_t)b*V_ + i0 + il)*H2_ + mc + mm];
        }
        if (tid < MC_) sw[tid] = outW[mc + tid];
        __syncthreads();

        #pragma unroll
        for (int il = 0; il < IL_; ++il) {
            float a = 0.f;
            #pragma unroll
            for (int mm = 0; mm < MC_; ++mm)
                a += fmaxf(sR[tid][mm] + sS[il][mm], 0.f) * sw[mm];
            acc[il] += a;
        }
    }

    const float ob = outB[0];
    #pragma unroll
    for (int il = 0; il < IL_; ++il) {
        float z = acc[il] + ob;
        out[((size_t)b*V_ + i0 + il)*V_ + tid] = 1.f / (1.f + expf(-z));
    }
}

// ---------------------------------------------------------------------------
// Launch
// ---------------------------------------------------------------------------
extern "C" void kernel_launch(void* const* d_in, const int* in_sizes, int n_in,
                              void* d_out, int out_size)
{
    const int*   adj   = (const int*)  d_in[0];
    const float* x0    = (const float*)d_in[1];
    const float* e     = (const float*)d_in[2];
    const float* ec1W1 = (const float*)d_in[3];
    const float* ec1b1 = (const float*)d_in[4];
    const float* ec1W2 = (const float*)d_in[5];
    const float* ec1b2 = (const float*)d_in[6];
    const float* ec2W1 = (const float*)d_in[7];
    const float* ec2b1 = (const float*)d_in[8];
    const float* ec2W2 = (const float*)d_in[9];
    const float* ec2b2 = (const float*)d_in[10];
    const float* h3W   = (const float*)d_in[11];
    const float* h3b   = (const float*)d_in[12];
    const float* outW  = (const float*)d_in[13];
    const float* outB  = (const float*)d_in[14];
    float* out = (float*)d_out;

    float *P, *Q, *X1, *X2, *R, *S;
    cudaGetSymbolAddress((void**)&P,  g_P);
    cudaGetSymbolAddress((void**)&Q,  g_Q);
    cudaGetSymbolAddress((void**)&X1, g_X1);
    cudaGetSymbolAddress((void**)&X2, g_X2);
    cudaGetSymbolAddress((void**)&R,  g_R);
    cudaGetSymbolAddress((void**)&S,  g_S);

    const size_t EC_SMEM =
        (size_t)(KE_*H_ + H_*H_ + JC_*ST_T + JC_*ST_E + H_ + H_ + V_) * sizeof(float);
    cudaFuncSetAttribute(ec_kernel, cudaFuncAttributeMaxDynamicSharedMemorySize,
                         (int)EC_SMEM);

    // EdgeConv #1 (C_in = 64); W1c = rows [2*64, 2*64+32) of ec1_W1
    pq_kernel<<<B_*V_/4, 128>>>(x0, ec1W1, ec1b1, 64, P, Q);
    ec_kernel<<<B_*V_, 256, EC_SMEM>>>(P, Q, e, ec1W1 + 2*64*H_, ec1W2, ec1b2, adj, X1);

    // EdgeConv #2 (C_in = 128); W1c = rows [2*128, 2*128+32) of ec2_W1
    pq_kernel<<<B_*V_/4, 128>>>(X1, ec2W1, ec2b1, 128, P, Q);
    ec_kernel<<<B_*V_, 256, EC_SMEM>>>(P, Q, e, ec2W1 + 2*128*H_, ec2W2, ec2b2, adj, X2);

    // Pair scoring
    rs_kernel<<<B_*V_/4, 256>>>(X2, h3W, h3b, R, S);
    dim3 pg(V_/IL_, B_);
    pair_kernel<<<pg, 256>>>(R, S, outW, outB, out);
}

// round 2
// speedup vs baseline: 1.3271x; 1.3271x over previous
#include <cuda_runtime.h>

// ---------------------------------------------------------------------------
// Shapes (fixed for this problem)
// ---------------------------------------------------------------------------
#define B_   4
#define V_   256
#define H_   128      // hidden dim of both EdgeConv layers
#define KE_  32       // edge-attr channels C2
#define JC_  128      // j-chunk processed per phase in ec_kernel
#define ST_T 132      // sT row stride (128 + 4 pad, float4-aligned)
#define ST_E 36       // sE row stride (32 + 4 pad, float4-aligned)
#define H2_  256      // pair-MLP hidden

// ---------------------------------------------------------------------------
// Device scratch (allocation-free rule: __device__ globals)
// ---------------------------------------------------------------------------
__device__ float g_P [B_*V_*H_];
__device__ float g_Q [B_*V_*H_];
__device__ float g_X1[B_*V_*H_];
__device__ float g_X2[B_*V_*H_];
__device__ float g_R [B_*V_*H2_];
__device__ float g_S [B_*V_*H2_];

// ---------------------------------------------------------------------------
// f32x2 packed-FMA helpers (FFMA2: 2 fp32 MACs per instruction on sm_103a)
// ---------------------------------------------------------------------------
using ull = unsigned long long;

__device__ __forceinline__ ull pack2(float x) {
    ull r; asm("mov.b64 %0, {%1, %1};" : "=l"(r) : "f"(x)); return r;
}
__device__ __forceinline__ ull ffma2(ull a, ull b, ull c) {
    ull d; asm("fma.rn.f32x2 %0, %1, %2, %3;" : "=l"(d) : "l"(a), "l"(b), "l"(c));
    return d;
}
__device__ __forceinline__ float2 unpack2(ull v) {
    float2 r; asm("mov.b64 {%0, %1}, %2;" : "=f"(r.x), "=f"(r.y) : "l"(v));
    return r;
}

// ---------------------------------------------------------------------------
// Per-node precompute for an EdgeConv layer:
//   P[n,h] = x[n,:] @ (W1[0:C] - W1[C:2C]) + b1   (x_i coefficient)
//   Q[n,h] = x[n,:] @  W1[C:2C]                    (x_j coefficient)
// ---------------------------------------------------------------------------
__global__ void pq_kernel(const float* __restrict__ x, const float* __restrict__ W1,
                          const float* __restrict__ b1, int C_in,
                          float* __restrict__ P, float* __restrict__ Q)
{
    __shared__ float sx[4][128];
    const int h = threadIdx.x;
    const int base = blockIdx.x * 4;
    #pragma unroll
    for (int r = 0; r < 4; ++r)
        if (h < C_in) sx[r][h] = x[(size_t)(base + r) * C_in + h];
    __syncthreads();

    float bb = b1[h];
    float p0 = bb, p1 = bb, p2 = bb, p3 = bb;
    float q0 = 0.f, q1 = 0.f, q2 = 0.f, q3 = 0.f;
    for (int c = 0; c < C_in; ++c) {
        float wa = W1[c * H_ + h];
        float wb = W1[(C_in + c) * H_ + h];
        float wd = wa - wb;
        p0 += sx[0][c] * wd;  q0 += sx[0][c] * wb;
        p1 += sx[1][c] * wd;  q1 += sx[1][c] * wb;
        p2 += sx[2][c] * wd;  q2 += sx[2][c] * wb;
        p3 += sx[3][c] * wd;  q3 += sx[3][c] * wb;
    }
    P[(size_t)(base+0)*H_ + h] = p0;  Q[(size_t)(base+0)*H_ + h] = q0;
    P[(size_t)(base+1)*H_ + h] = p1;  Q[(size_t)(base+1)*H_ + h] = q1;
    P[(size_t)(base+2)*H_ + h] = p2;  Q[(size_t)(base+2)*H_ + h] = q2;
    P[(size_t)(base+3)*H_ + h] = p3;  Q[(size_t)(base+3)*H_ + h] = q3;
}

// ---------------------------------------------------------------------------
// Fused EdgeConv main kernel. One CTA per (b, i).
//   T[j,c] = relu(P[i,c] + Q[j,c] + e[b,i,j,:] @ W1c)     (phase 1, K=32)
//   H[j,c] = relu(T[j,:] @ W2 + b2)                        (phase 2, K=128)
//   Xout[b,i,c] = masked-max_j H[j,c]   (adj mask; all-masked -> 0)
// 256 threads, 16x16 thread grid, 8x8 register tiles, f32x2 packed FMAs.
// k unrolled x4 with float4 A-operand loads (LDS.128) to cut LDS issue count.
// ---------------------------------------------------------------------------
__global__ void __launch_bounds__(256, 1)
ec_kernel(const float* __restrict__ Pg, const float* __restrict__ Qg,
          const float* __restrict__ E, const float* __restrict__ W1c,
          const float* __restrict__ W2, const float* __restrict__ b2,
          const int* __restrict__ adj, float* __restrict__ Xout)
{
    extern __shared__ float sm[];
    float* sW1c = sm;                        // 32*128      = 4096
    float* sW2  = sW1c + KE_*H_;             // 128*128     = 16384
    float* sT   = sW2  + H_*H_;              // 128*132     = 16896
    float* sE   = sT   + JC_*ST_T;           // 128*36      = 4608
    float* sP   = sE   + JC_*ST_E;           // 128
    float* sB2  = sP   + H_;                 // 128
    int*   sAdj = (int*)(sB2 + H_);          // 256
    float* sRed = sE;                        // reuse (needs 16*128 <= 4608)

    const int tid = threadIdx.x;
    const int bi  = blockIdx.x;              // b*V + i
    const int b   = bi >> 8;

    // stage weights (vectorized)
    {
        const float4* w1 = (const float4*)W1c;
        float4* d1 = (float4*)sW1c;
        #pragma unroll
        for (int idx = tid; idx < KE_*H_/4; idx += 256) d1[idx] = w1[idx];
        const float4* w2 = (const float4*)W2;
        float4* d2 = (float4*)sW2;
        #pragma unroll 4
        for (int idx = tid; idx < H_*H_/4; idx += 256) d2[idx] = w2[idx];
    }
    if (tid < H_) { sP[tid] = Pg[(size_t)bi*H_ + tid]; sB2[tid] = b2[tid]; }
    sAdj[tid] = adj[(size_t)bi*V_ + tid];

    const int ty = tid >> 4, tx = tid & 15;
    const int j0 = ty << 3, c0 = tx << 3;

    float rmax[8];
    #pragma unroll
    for (int p = 0; p < 8; ++p) rmax[p] = -1e9f;

    for (int chunk = 0; chunk < V_/JC_; ++chunk) {
        const int jbase = chunk * JC_;
        __syncthreads();
        // load E chunk (rows jbase..jbase+127) into sE[j][k] (float4)
        {
            const float4* Erow = (const float4*)(E + ((size_t)bi * V_ + jbase) * KE_);
            #pragma unroll
            for (int idx = tid; idx < JC_*KE_/4; idx += 256) {
                int j = idx >> 3, k4 = (idx & 7);
                *(float4*)&sE[j*ST_E + k4*4] = Erow[idx];
            }
        }
        __syncthreads();

        // ---- phase 1: E @ W1c (K=32), k unrolled x4 ----
        ull acc[8][4];
        #pragma unroll
        for (int jj = 0; jj < 8; ++jj)
            #pragma unroll
            for (int p = 0; p < 4; ++p) acc[jj][p] = 0ULL;

        #pragma unroll 2
        for (int k = 0; k < KE_; k += 4) {
            float4 av[8];
            #pragma unroll
            for (int jj = 0; jj < 8; ++jj)
                av[jj] = *(const float4*)&sE[(j0+jj)*ST_E + k];
            #pragma unroll
            for (int kk = 0; kk < 4; ++kk) {
                const ulonglong2 bb0 = *(const ulonglong2*)&sW1c[(k+kk)*H_ + c0];
                const ulonglong2 bb1 = *(const ulonglong2*)&sW1c[(k+kk)*H_ + c0 + 4];
                #pragma unroll
                for (int jj = 0; jj < 8; ++jj) {
                    float as = (kk==0) ? av[jj].x : (kk==1) ? av[jj].y
                             : (kk==2) ? av[jj].z : av[jj].w;
                    ull a2 = pack2(as);
                    acc[jj][0] = ffma2(a2, bb0.x, acc[jj][0]);
                    acc[jj][1] = ffma2(a2, bb0.y, acc[jj][1]);
                    acc[jj][2] = ffma2(a2, bb1.x, acc[jj][2]);
                    acc[jj][3] = ffma2(a2, bb1.y, acc[jj][3]);
                }
            }
        }

        // epilogue: T = relu(acc + P + Q) -> sT (float4 stores)
        {
            float4 pv0 = *(const float4*)&sP[c0];
            float4 pv1 = *(const float4*)&sP[c0 + 4];
            #pragma unroll
            for (int jj = 0; jj < 8; ++jj) {
                const float* q = Qg + ((size_t)b*V_ + jbase + j0 + jj)*H_ + c0;
                float4 q0v = *(const float4*)(q);
                float4 q1v = *(const float4*)(q + 4);
                float2 a0 = unpack2(acc[jj][0]);
                float2 a1 = unpack2(acc[jj][1]);
                float2 a2 = unpack2(acc[jj][2]);
                float2 a3 = unpack2(acc[jj][3]);
                float4 t0, t1;
                t0.x = fmaxf(a0.x + pv0.x + q0v.x, 0.f);
                t0.y = fmaxf(a0.y + pv0.y + q0v.y, 0.f);
                t0.z = fmaxf(a1.x + pv0.z + q0v.z, 0.f);
                t0.w = fmaxf(a1.y + pv0.w + q0v.w, 0.f);
                t1.x = fmaxf(a2.x + pv1.x + q1v.x, 0.f);
                t1.y = fmaxf(a2.y + pv1.y + q1v.y, 0.f);
                t1.z = fmaxf(a3.x + pv1.z + q1v.z, 0.f);
                t1.w = fmaxf(a3.y + pv1.w + q1v.w, 0.f);
                float* trow = sT + (j0+jj)*ST_T + c0;
                *(float4*)(trow)     = t0;
                *(float4*)(trow + 4) = t1;
            }
        }
        __syncthreads();

        // ---- phase 2: T @ W2 (K=128), k unrolled x4 ----
        #pragma unroll
        for (int jj = 0; jj < 8; ++jj)
            #pragma unroll
            for (int p = 0; p < 4; ++p) acc[jj][p] = 0ULL;

        #pragma unroll 2
        for (int k = 0; k < H_; k += 4) {
            float4 av[8];
            #pragma unroll
            for (int jj = 0; jj < 8; ++jj)
                av[jj] = *(const float4*)&sT[(j0+jj)*ST_T + k];
            #pragma unroll
            for (int kk = 0; kk < 4; ++kk) {
                const ulonglong2 bb0 = *(const ulonglong2*)&sW2[(k+kk)*H_ + c0];
                const ulonglong2 bb1 = *(const ulonglong2*)&sW2[(k+kk)*H_ + c0 + 4];
                #pragma unroll
                for (int jj = 0; jj < 8; ++jj) {
                    float as = (kk==0) ? av[jj].x : (kk==1) ? av[jj].y
                             : (kk==2) ? av[jj].z : av[jj].w;
                    ull a2 = pack2(as);
                    acc[jj][0] = ffma2(a2, bb0.x, acc[jj][0]);
                    acc[jj][1] = ffma2(a2, bb0.y, acc[jj][1]);
                    acc[jj][2] = ffma2(a2, bb1.x, acc[jj][2]);
                    acc[jj][3] = ffma2(a2, bb1.y, acc[jj][3]);
                }
            }
        }

        // epilogue: relu(+b2), adjacency-masked running max over j
        #pragma unroll
        for (int jj = 0; jj < 8; ++jj) {
            if (sAdj[jbase + j0 + jj] > 0) {
                #pragma unroll
                for (int p = 0; p < 4; ++p) {
                    float2 hv = unpack2(acc[jj][p]);
                    float h0 = fmaxf(hv.x + sB2[c0+2*p],   0.f);
                    float h1 = fmaxf(hv.y + sB2[c0+2*p+1], 0.f);
                    rmax[2*p]   = fmaxf(rmax[2*p],   h0);
                    rmax[2*p+1] = fmaxf(rmax[2*p+1], h1);
                }
            }
        }
    }

    // cross-thread (over ty / j-tiles) max reduction
    __syncthreads();
    #pragma unroll
    for (int p = 0; p < 8; ++p) sRed[ty*H_ + c0 + p] = rmax[p];
    __syncthreads();
    for (int s = 8; s > 0; s >>= 1) {
        if (ty < s) {
            #pragma unroll
            for (int p = 0; p < 8; ++p) {
                float a = sRed[ty*H_ + c0 + p];
                float o = sRed[(ty+s)*H_ + c0 + p];
                sRed[ty*H_ + c0 + p] = fmaxf(a, o);
            }
        }
        __syncthreads();
    }
    if (ty == 0) {
        #pragma unroll
        for (int p = 0; p < 8; ++p) {
            float v = sRed[c0 + p];
            Xout[(size_t)bi*H_ + c0 + p] = (v < -1e8f) ? 0.f : v;
        }
    }
}

// ---------------------------------------------------------------------------
// Pair-MLP precompute:
//   R[n,m] = x2[n,:] @ h3_W[0:128,  m]            (x_j part)
//   S[n,m] = x2[n,:] @ h3_W[128:256,m] + h3_b[m]  (x_i part)
// ---------------------------------------------------------------------------
__global__ void rs_kernel(const float* __restrict__ x, const float* __restrict__ W3,
                          const float* __restrict__ b3,
                          float* __restrict__ R, float* __restrict__ S)
{
    __shared__ float sx[4][128];
    const int m = threadIdx.x;
    const int base = blockIdx.x * 4;
    if (m < 128) {
        #pragma unroll
        for (int r = 0; r < 4; ++r)
            sx[r][m] = x[(size_t)(base + r) * H_ + m];
    }
    __syncthreads();

    float r0 = 0.f, r1 = 0.f, r2 = 0.f, r3 = 0.f;
    float bb = b3[m];
    float s0 = bb, s1 = bb, s2 = bb, s3 = bb;
    for (int c = 0; c < 128; ++c) {
        float wa = W3[c * H2_ + m];
        float wb = W3[(128 + c) * H2_ + m];
        r0 += sx[0][c]*wa;  s0 += sx[0][c]*wb;
        r1 += sx[1][c]*wa;  s1 += sx[1][c]*wb;
        r2 += sx[2][c]*wa;  s2 += sx[2][c]*wb;
        r3 += sx[3][c]*wa;  s3 += sx[3][c]*wb;
    }
    R[(size_t)(base+0)*H2_ + m] = r0;  S[(size_t)(base+0)*H2_ + m] = s0;
    R[(size_t)(base+1)*H2_ + m] = r1;  S[(size_t)(base+1)*H2_ + m] = s1;
    R[(size_t)(base+2)*H2_ + m] = r2;  S[(size_t)(base+2)*H2_ + m] = s2;
    R[(size_t)(base+3)*H2_ + m] = r3;  S[(size_t)(base+3)*H2_ + m] = s3;
}

// ---------------------------------------------------------------------------
// Pair scoring: out[b,i,j] = sigmoid( sum_m relu(R[j,m]+S[i,m]) * outW[m] + outB )
// ---------------------------------------------------------------------------
#define IL_ 8
#define MC_ 32

__global__ void __launch_bounds__(256)
pair_kernel(const float* __restrict__ R, const float* __restrict__ S,
            const float* __restrict__ outW, const float* __restrict__ outB,
            float* __restrict__ out)
{
    __shared__ float sR[V_][MC_ + 1];
    __shared__ float sS[IL_][MC_ + 1];
    __shared__ float sw[MC_];

    const int tid = threadIdx.x;   // == j
    const int b   = blockIdx.y;
    const int i0  = blockIdx.x * IL_;

    float acc[IL_];
    #pragma unroll
    for (int il = 0; il < IL_; ++il) acc[il] = 0.f;

    for (int mc = 0; mc < H2_; mc += MC_) {
        __syncthreads();
        #pragma unroll 4
        for (int idx = tid; idx < V_*MC_; idx += 256) {
            int j = idx >> 5, mm = idx & (MC_-1);
            sR[j][mm] = R[((size_t)b*V_ + j)*H2_ + mc + mm];
        }
        if (tid < IL_*MC_) {
            int il = tid >> 5, mm = tid & (MC_-1);
            sS[il][mm] = S[((size_t)b*V_ + i0 + il)*H2_ + mc + mm];
        }
        if (tid < MC_) sw[tid] = outW[mc + tid];
        __syncthreads();

        #pragma unroll
        for (int il = 0; il < IL_; ++il) {
            float a = 0.f;
            #pragma unroll
            for (int mm = 0; mm < MC_; ++mm)
                a += fmaxf(sR[tid][mm] + sS[il][mm], 0.f) * sw[mm];
            acc[il] += a;
        }
    }

    const float ob = outB[0];
    #pragma unroll
    for (int il = 0; il < IL_; ++il) {
        float z = acc[il] + ob;
        out[((size_t)b*V_ + i0 + il)*V_ + tid] = 1.f / (1.f + expf(-z));
    }
}

// ---------------------------------------------------------------------------
// Launch
// ---------------------------------------------------------------------------
extern "C" void kernel_launch(void* const* d_in, const int* in_sizes, int n_in,
                              void* d_out, int out_size)
{
    const int*   adj   = (const int*)  d_in[0];
    const float* x0    = (const float*)d_in[1];
    const float* e     = (const float*)d_in[2];
    const float* ec1W1 = (const float*)d_in[3];
    const float* ec1b1 = (const float*)d_in[4];
    const float* ec1W2 = (const float*)d_in[5];
    const float* ec1b2 = (const float*)d_in[6];
    const float* ec2W1 = (const float*)d_in[7];
    const float* ec2b1 = (const float*)d_in[8];
    const float* ec2W2 = (const float*)d_in[9];
    const float* ec2b2 = (const float*)d_in[10];
    const float* h3W   = (const float*)d_in[11];
    const float* h3b   = (const float*)d_in[12];
    const float* outW  = (const float*)d_in[13];
    const float* outB  = (const float*)d_in[14];
    float* out = (float*)d_out;

    float *P, *Q, *X1, *X2, *R, *S;
    cudaGetSymbolAddress((void**)&P,  g_P);
    cudaGetSymbolAddress((void**)&Q,  g_Q);
    cudaGetSymbolAddress((void**)&X1, g_X1);
    cudaGetSymbolAddress((void**)&X2, g_X2);
    cudaGetSymbolAddress((void**)&R,  g_R);
    cudaGetSymbolAddress((void**)&S,  g_S);

    const size_t EC_SMEM =
        (size_t)(KE_*H_ + H_*H_ + JC_*ST_T + JC_*ST_E + H_ + H_ + V_) * sizeof(float);
    cudaFuncSetAttribute(ec_kernel, cudaFuncAttributeMaxDynamicSharedMemorySize,
                         (int)EC_SMEM);

    // EdgeConv #1 (C_in = 64); W1c = rows [2*64, 2*64+32) of ec1_W1
    pq_kernel<<<B_*V_/4, 128>>>(x0, ec1W1, ec1b1, 64, P, Q);
    ec_kernel<<<B_*V_, 256, EC_SMEM>>>(P, Q, e, ec1W1 + 2*64*H_, ec1W2, ec1b2, adj, X1);

    // EdgeConv #2 (C_in = 128); W1c = rows [2*128, 2*128+32) of ec2_W1
    pq_kernel<<<B_*V_/4, 128>>>(X1, ec2W1, ec2b1, 128, P, Q);
    ec_kernel<<<B_*V_, 256, EC_SMEM>>>(P, Q, e, ec2W1 + 2*128*H_, ec2W2, ec2b2, adj, X2);

    // Pair scoring
    rs_kernel<<<B_*V_/4, 256>>>(X2, h3W, h3b, R, S);
    dim3 pg(V_/IL_, B_);
    pair_kernel<<<pg, 256>>>(R, S, outW, outB, out);
}